// round 16
// baseline (speedup 1.0000x reference)
#include <cuda_runtime.h>
#include <cuda_bf16.h>
#include <cuda_pipeline.h>

// Problem constants (constexpr, not macros)
constexpr int CB  = 2;     // batch
constexpr int CL  = 128;   // seq len
constexpr int CD  = 256;   // model dim
constexpr int CH  = 8;     // heads
constexpr int CDK = 32;    // head dim
constexpr float C_EPS = 1e-6f;
constexpr float C_INV_TEMP = 0.17677669529663687f;   // 1/sqrt(32)

// Scratch (allocation-free rule: __device__ globals)
__device__ float g_pq[CB * CL * CD];
__device__ float g_pk[CB * CL * CD];
__device__ float g_pv[CB * CL * CD];
__device__ float g_dotqk[CB * CH * CL];
__device__ float g_outhead[CB * CL * CD];

extern __shared__ float sm_dyn[];

// ---------------------------------------------------------------------------
// K1: uniform projection GEMM.  grid=(8,8,3), block=512, dyn smem 68KB.
// __launch_bounds__(512, 2): 68KB/block -> 2-3 blocks/SM co-resident, so
// one block's cp.async prologue overlaps another's FMA loop (the R13/R15
// monolith had 1 block/SM, 4 warps/SMSP, and was latency-starved).
//   mat=0: pq = LN(q) @ Wq    mat=1: pk = k @ Wk    mat=2: pv = v @ Wv
// 32x32 tile, K=256 resident, 2r x 2c microtile, split-K x2.
// smem: A4 f4[64*32] @0 (32KB) | Bs[256*32] @8192 (32KB) | red[1024] @16384
// ---------------------------------------------------------------------------
__global__ __launch_bounds__(512, 2)
void ct_gemm_kernel(const float* __restrict__ qin,
                    const float* __restrict__ kin,
                    const float* __restrict__ vin,
                    const float* __restrict__ Wq,
                    const float* __restrict__ Wk,
                    const float* __restrict__ Wv,
                    const float* __restrict__ ln_g,
                    const float* __restrict__ ln_b) {
    const int mat = blockIdx.z;
    const float* A_g; const float* W_g; float* C;
    if (mat == 0)      { A_g = qin; W_g = Wq; C = g_pq; }
    else if (mat == 1) { A_g = kin; W_g = Wk; C = g_pk; }
    else               { A_g = vin; W_g = Wv; C = g_pv; }

    float4* A4  = (float4*)sm_dyn;          // [kk4(64)][row(32)]
    float*  Bs  = sm_dyn + 8192;            // [k(256)][col(32)]
    float*  red = sm_dyn + 16384;           // [1024]

    int tid = threadIdx.x;
    int m0 = blockIdx.y * 32, n0 = blockIdx.x * 32;

    // ---- issue all async copies up front -------------------------------
    {
        int r = tid & 31, k4b = tid >> 5;       // k4b 0..15
#pragma unroll
        for (int it = 0; it < 4; it++) {
            int kk = k4b + it * 16;             // 0..63
            __pipeline_memcpy_async(&A4[kk * 32 + r], &A_g[(m0 + r) * CD + kk * 4], 16);
        }
        int c4 = tid & 7, kb = tid >> 3;        // kb 0..63
#pragma unroll
        for (int it = 0; it < 4; it++) {
            int k = kb + it * 64;               // 0..255
            __pipeline_memcpy_async(&Bs[k * 32 + c4 * 4], &W_g[k * CD + n0 + c4 * 4], 16);
        }
    }
    __pipeline_commit();

    // ---- LN stats from global while copies fly (mat==0 only) -----------
    // 16 warps, 32 rows: warp w owns rows 2w, 2w+1.
    int w = tid >> 5, lane = tid & 31;
    float mu0 = 0.f, rs0 = 0.f, mu1 = 0.f, rs1 = 0.f;
    if (mat == 0) {
#pragma unroll
        for (int half = 0; half < 2; half++) {
            int rr = 2 * w + half;
            const float* rowp = qin + (m0 + rr) * CD;
            float s1 = 0.f, s2 = 0.f;
#pragma unroll
            for (int e = 0; e < 8; e++) {
                float x = rowp[lane + 32 * e];
                s1 += x; s2 += x * x;
            }
#pragma unroll
            for (int o = 16; o > 0; o >>= 1) {
                s1 += __shfl_xor_sync(0xFFFFFFFFu, s1, o);
                s2 += __shfl_xor_sync(0xFFFFFFFFu, s2, o);
            }
            float mu  = s1 * (1.0f / 256.0f);
            float var = s2 * (1.0f / 256.0f) - mu * mu;
            float rs  = rsqrtf(var + C_EPS);
            if (half == 0) { mu0 = mu; rs0 = rs; }
            else           { mu1 = mu; rs1 = rs; }
        }
    }

    __pipeline_wait_prior(0);
    __syncthreads();

    // ---- in-smem LN transform of A (mat==0): warp w -> rows 2w,2w+1 ----
    if (mat == 0) {
#pragma unroll
        for (int half = 0; half < 2; half++) {
            int rr = 2 * w + half;
            float mu = half ? mu1 : mu0;
            float rs = half ? rs1 : rs0;
#pragma unroll
            for (int c = 0; c < 2; c++) {
                int kk = lane + c * 32;          // 0..63
                float4 p  = A4[kk * 32 + rr];
                float4 g4 = ((const float4*)ln_g)[kk];
                float4 b4 = ((const float4*)ln_b)[kk];
                p.x = (p.x - mu) * rs * g4.x + b4.x;
                p.y = (p.y - mu) * rs * g4.y + b4.y;
                p.z = (p.z - mu) * rs * g4.z + b4.z;
                p.w = (p.w - mu) * rs * g4.w + b4.w;
                A4[kk * 32 + rr] = p;
            }
        }
        __syncthreads();
    }

    // ---- compute: 2r x 2c microtile, split-K x2 ------------------------
    int g   = tid >> 8;                 // split-K half
    int idx = tid & 255;
    int rg  = idx >> 4;                 // 0..15 -> rows 2rg, 2rg+1
    int cpp = idx & 15;                 // 0..15 -> cols 2cpp, 2cpp+1
    int r0 = rg * 2, r1 = r0 + 1, c0 = cpp * 2;
    int kbase = g * 32;

    float a00 = 0.f, a01 = 0.f, a10 = 0.f, a11 = 0.f;
#pragma unroll 8
    for (int kk = 0; kk < 32; kk++) {
        int kk4 = kbase + kk;
        float4 ar0 = A4[kk4 * 32 + r0];
        float4 ar1 = A4[kk4 * 32 + r1];
        const float* brow = &Bs[(kk4 * 4) * 32 + c0];
        float2 b0 = *(const float2*)&brow[0 * 32];
        float2 b1 = *(const float2*)&brow[1 * 32];
        float2 b2 = *(const float2*)&brow[2 * 32];
        float2 b3 = *(const float2*)&brow[3 * 32];
        a00 += ar0.x * b0.x; a01 += ar0.x * b0.y;
        a10 += ar1.x * b0.x; a11 += ar1.x * b0.y;
        a00 += ar0.y * b1.x; a01 += ar0.y * b1.y;
        a10 += ar1.y * b1.x; a11 += ar1.y * b1.y;
        a00 += ar0.z * b2.x; a01 += ar0.z * b2.y;
        a10 += ar1.z * b2.x; a11 += ar1.z * b2.y;
        a00 += ar0.w * b3.x; a01 += ar0.w * b3.y;
        a10 += ar1.w * b3.x; a11 += ar1.w * b3.y;
    }

    // ---- combine split-K halves and store ------------------------------
    if (g == 1) {
        red[idx * 4 + 0] = a00; red[idx * 4 + 1] = a01;
        red[idx * 4 + 2] = a10; red[idx * 4 + 3] = a11;
    }
    __syncthreads();
    if (g == 0) {
        a00 += red[idx * 4 + 0]; a01 += red[idx * 4 + 1];
        a10 += red[idx * 4 + 2]; a11 += red[idx * 4 + 3];
        *(float2*)&C[(m0 + r0) * CD + n0 + c0] = make_float2(a00, a01);
        *(float2*)&C[(m0 + r1) * CD + n0 + c0] = make_float2(a10, a11);
    }
}

// ---------------------------------------------------------------------------
// K2: dot_qk[b,h,j] = sum_d pq[b,j,h,d]*pk[b,j,h,d].  One warp per (b,h,j).
// grid=256, block=256.
// ---------------------------------------------------------------------------
__global__ __launch_bounds__(256)
void ct_dotqk_kernel() {
    int idx  = blockIdx.x * 8 + (threadIdx.x >> 5);   // b*1024 + h*128 + j
    int lane = threadIdx.x & 31;
    int b = idx >> 10;
    int rem = idx & 1023;
    int h = rem >> 7;
    int j = rem & 127;
    float v = g_pq[(b * CL + j) * CD + h * CDK + lane] *
              g_pk[(b * CL + j) * CD + h * CDK + lane];
#pragma unroll
    for (int o = 16; o > 0; o >>= 1) v += __shfl_xor_sync(0xFFFFFFFFu, v, o);
    if (lane == 0) g_dotqk[idx] = v;
}

// ---------------------------------------------------------------------------
// K3: fused attention per (b,i).  Prologue computes time-kernel tables
// (chi, lb) in smem; warp h owns head h: shuffle-only softmax, attn write,
// V-reduction.  grid=256 (b*128+i), block=256, static smem.
// ---------------------------------------------------------------------------
__global__ __launch_bounds__(256)
void ct_attn_kernel(const float* __restrict__ t,
                    const float* __restrict__ omega,
                    const float* __restrict__ s,
                    float* __restrict__ attn_out) {
    int bid = blockIdx.x;
    int b = bid >> 7;
    int i = bid & 127;
    int tid = threadIdx.x;
    int h = tid >> 5;
    int lane = tid & 31;
    int j0 = lane * 4;

    __shared__ float sh_lb[128];        // omega * INV_TEMP * psi
    __shared__ float sh_chi[128];       // sum_r exp(-dt*s_r)
    __shared__ float sh_ws[8][128];

    if (tid < 128) {
        int j = tid;
        float s0 = s[0], s1 = s[1], s2 = s[2], s3 = s[3];
        float dt = fabsf(t[b * CL + i] - t[b * CL + j]);
        float c0 = __expf(-dt * s0), c1 = __expf(-dt * s1);
        float c2 = __expf(-dt * s2), c3 = __expf(-dt * s3);
        sh_chi[j] = (c0 + c1) + (c2 + c3);
        float psi = (c0 * c0 + c1 * c1) + (c2 * c2 + c3 * c3);
        sh_lb[j] = omega[(b * CL + i) * CL + j] * C_INV_TEMP * psi;
    }
    __syncthreads();

    float4 dq = *(const float4*)&g_dotqk[b * (CH * CL) + h * CL + j0];
    float4 lb = *(const float4*)&sh_lb[j0];
    float4 ch = *(const float4*)&sh_chi[j0];

    float l0 = (j0 + 0 <= i) ? lb.x * dq.x : -1e9f;
    float l1 = (j0 + 1 <= i) ? lb.y * dq.y : -1e9f;
    float l2 = (j0 + 2 <= i) ? lb.z * dq.z : -1e9f;
    float l3 = (j0 + 3 <= i) ? lb.w * dq.w : -1e9f;

    float m = fmaxf(fmaxf(l0, l1), fmaxf(l2, l3));
#pragma unroll
    for (int o = 16; o > 0; o >>= 1)
        m = fmaxf(m, __shfl_xor_sync(0xFFFFFFFFu, m, o));

    float e0 = __expf(l0 - m), e1 = __expf(l1 - m);
    float e2 = __expf(l2 - m), e3 = __expf(l3 - m);
    float su = (e0 + e1) + (e2 + e3);
#pragma unroll
    for (int o = 16; o > 0; o >>= 1)
        su += __shfl_xor_sync(0xFFFFFFFFu, su, o);

    float inv = 1.0f / su;
    float4 a4 = make_float4(e0 * inv, e1 * inv, e2 * inv, e3 * inv);
    *(float4*)&attn_out[((b * CH + h) * CL + i) * CL + j0] = a4;

    float4 w4 = make_float4(a4.x * ch.x, a4.y * ch.y, a4.z * ch.z, a4.w * ch.w);
    *(float4*)&sh_ws[h][j0] = w4;
    __syncwarp();

    // V reduction: outhead[b,i,h,d] = sum_j ws[h][j] * pv[b,j,h,d]
    const float* pvp = g_pv + b * CL * CD + h * CDK + lane;
    const float* wsp = sh_ws[h];
    float a0 = 0.f, a1 = 0.f, a2 = 0.f, a3 = 0.f;
#pragma unroll 8
    for (int j = 0; j < 128; j += 4) {
        a0 += wsp[j + 0] * pvp[(j + 0) * CD];
        a1 += wsp[j + 1] * pvp[(j + 1) * CD];
        a2 += wsp[j + 2] * pvp[(j + 2) * CD];
        a3 += wsp[j + 3] * pvp[(j + 3) * CD];
    }
    g_outhead[bid * CD + h * CDK + lane] = (a0 + a1) + (a2 + a3);
}

// ---------------------------------------------------------------------------
// K4: out = outhead @ fc_w + fc_b + q (residual).
// grid=(8,16), block=512: split-K x2 (each half does K=128), smem combine.
// ---------------------------------------------------------------------------
__global__ __launch_bounds__(512, 2)
void ct_final_kernel(const float* __restrict__ W,
                     const float* __restrict__ bias,
                     const float* __restrict__ resid,
                     float* __restrict__ out) {
    float4* A4  = (float4*)sm_dyn;
    float*  Bs  = sm_dyn + 4096;
    float*  red = sm_dyn + 4096 + 8192;

    int tid = threadIdx.x;
    int m0 = blockIdx.y * 16, n0 = blockIdx.x * 32;

    {
        int r = tid & 15, kk4g = tid >> 4;       // 0..31
#pragma unroll
        for (int it = 0; it < 2; it++) {
            int kk = kk4g + it * 32;
            __pipeline_memcpy_async(&A4[kk * 16 + r],
                                    &g_outhead[(m0 + r) * CD + kk * 4], 16);
        }
        int c4 = tid & 7, k0 = tid >> 3;         // 0..63
#pragma unroll
        for (int it = 0; it < 4; it++) {
            int kx = k0 + it * 64;
            __pipeline_memcpy_async(&Bs[kx * 32 + c4 * 4],
                                    &W[kx * CD + n0 + c4 * 4], 16);
        }
    }
    __pipeline_commit();
    __pipeline_wait_prior(0);
    __syncthreads();

    int g   = tid >> 8;                  // split-K half
    int idx = tid & 255;
    int lr  = idx >> 4;
    int lc2 = (idx & 15) * 2;
    float acc0 = 0.f, acc1 = 0.f;
    int base = g * 32;

#pragma unroll 16
    for (int kk = 0; kk < 32; kk++) {
        int kk4 = base + kk;
        float4 a4 = A4[kk4 * 16 + lr];
        const float* brow = &Bs[(kk4 * 4) * 32 + lc2];
        float2 b0 = *(const float2*)&brow[0 * 32];
        float2 b1 = *(const float2*)&brow[1 * 32];
        float2 b2 = *(const float2*)&brow[2 * 32];
        float2 b3 = *(const float2*)&brow[3 * 32];
        acc0 += a4.x * b0.x; acc1 += a4.x * b0.y;
        acc0 += a4.y * b1.x; acc1 += a4.y * b1.y;
        acc0 += a4.z * b2.x; acc1 += a4.z * b2.y;
        acc0 += a4.w * b3.x; acc1 += a4.w * b3.y;
    }

    if (g == 1) {
        red[idx * 2 + 0] = acc0;
        red[idx * 2 + 1] = acc1;
    }
    __syncthreads();
    if (g == 0) {
        acc0 += red[idx * 2 + 0];
        acc1 += red[idx * 2 + 1];
        int row = m0 + lr, col = n0 + lc2;
        float2 bi = *(const float2*)&bias[col];
        float2 re = *(const float2*)&resid[row * CD + col];
        *(float2*)&out[row * CD + col] =
            make_float2(acc0 + bi.x + re.x, acc1 + bi.y + re.y);
    }
}

// ---------------------------------------------------------------------------
// Launch.  Inputs: q,k,v,t,omega,mask,Wq,Wk,Wv,s,fc_w,fc_b,ln_g,ln_b
// Output: out (65536 f32) then attn (262144 f32)
// ---------------------------------------------------------------------------
extern "C" void kernel_launch(void* const* d_in, const int* in_sizes, int n_in,
                              void* d_out, int out_size) {
    const float* q     = (const float*)d_in[0];
    const float* k     = (const float*)d_in[1];
    const float* v     = (const float*)d_in[2];
    const float* t     = (const float*)d_in[3];
    const float* omega = (const float*)d_in[4];
    // d_in[5] = mask (causal triu) -- applied analytically
    const float* Wq    = (const float*)d_in[6];
    const float* Wk    = (const float*)d_in[7];
    const float* Wv    = (const float*)d_in[8];
    const float* s     = (const float*)d_in[9];
    const float* fc_w  = (const float*)d_in[10];
    const float* fc_b  = (const float*)d_in[11];
    const float* ln_g  = (const float*)d_in[12];
    const float* ln_b  = (const float*)d_in[13];

    float* out      = (float*)d_out;
    float* attn_out = out + CB * CL * CD;

    // 68KB dynamic smem for the GEMM (2-3 blocks/SM); 50KB for final.
    cudaFuncSetAttribute(ct_gemm_kernel,
                         cudaFuncAttributeMaxDynamicSharedMemorySize, 72 * 1024);
    cudaFuncSetAttribute(ct_final_kernel,
                         cudaFuncAttributeMaxDynamicSharedMemorySize, 50 * 1024);

    ct_gemm_kernel<<<dim3(8, 8, 3), 512, 17408 * 4>>>(q, k, v, Wq, Wk, Wv, ln_g, ln_b);
    ct_dotqk_kernel<<<256, 256>>>();
    ct_attn_kernel<<<CB * CL, 256>>>(t, omega, s, attn_out);
    ct_final_kernel<<<dim3(8, 16), 512, 50 * 1024>>>(fc_w, fc_b, q, out);
}